// round 8
// baseline (speedup 1.0000x reference)
#include <cuda_runtime.h>
#include <cstdint>
#include <math.h>

// ---------------- problem constants ----------------
#define QLEN    1024
#define BATCH   4
#define DMODEL  1024
#define NHEAD   16
#define HDIM    64
#define MEMLEN  512
#define KLENC   1536
#define MLPD    4096
#define ATT_SCALE 0.125f
#define NROWS   4096
#define KROWS   6144

// ---------------- scratch ----------------
__device__ __align__(16) float g_cat[(size_t)KROWS * DMODEL];
__device__ __align__(16) float g_qkv[(size_t)KROWS * 3 * DMODEL];
__device__ __align__(16) float g_rh [(size_t)KLENC * DMODEL];
__device__ __align__(16) float g_S  [(size_t)64 * QLEN * KLENC];
__device__ __align__(16) float g_BD [(size_t)64 * QLEN * KLENC];
__device__ __align__(16) float g_Qu [(size_t)64 * QLEN * HDIM];
__device__ __align__(16) float g_Qv [(size_t)64 * QLEN * HDIM];
__device__ __align__(16) float g_rsum[(size_t)64 * QLEN];
__device__ __align__(16) float g_ctx[(size_t)NROWS * DMODEL];
__device__ __align__(16) float g_y  [(size_t)NROWS * DMODEL];
__device__ __align__(16) float g_x  [(size_t)NROWS * DMODEL];
__device__ __align__(16) float g_h  [(size_t)NROWS * MLPD];
__device__ __align__(16) float g_y2 [(size_t)NROWS * DMODEL];

// ---------------- helpers ----------------
__device__ __forceinline__ uint32_t smem_u32(const void* p) {
    uint32_t a;
    asm("{ .reg .u64 t; cvta.to.shared.u64 t, %1; cvt.u32.u64 %0, t; }" : "=r"(a) : "l"(p));
    return a;
}
__device__ __forceinline__ uint32_t tf32u(float x) {
    uint32_t u;
    asm("cvt.rna.tf32.f32 %0, %1;" : "=r"(u) : "f"(x));
    return u;
}
__device__ __forceinline__ void cpa16(uint32_t s, const void* g) {
    asm volatile("cp.async.cg.shared.global [%0], [%1], 16;" :: "r"(s), "l"(g));
}
__device__ __forceinline__ void cpcommit() {
    asm volatile("cp.async.commit_group;" ::: "memory");
}
__device__ __forceinline__ void mma_tf32(float* c, const uint32_t* a, const uint32_t* b)
{
    asm volatile(
        "mma.sync.aligned.m16n8k8.row.col.f32.tf32.tf32.f32 "
        "{%0,%1,%2,%3}, {%4,%5,%6,%7}, {%8,%9}, {%0,%1,%2,%3};"
        : "+f"(c[0]), "+f"(c[1]), "+f"(c[2]), "+f"(c[3])
        : "r"(a[0]), "r"(a[1]), "r"(a[2]), "r"(a[3]), "r"(b[0]), "r"(b[1]));
}

// K-chunk = 32 everywhere. A smem tile: [128][36]; NT B tile: [128][36]; NN B tile: [32][132].
#define AP 36
#define BP_NN 132

// ============ mm_nn: C[M,N] = A[M,K] @ B[K,N], B row-major [K,N] ============
#define STG_NN (128 * AP + 32 * BP_NN)          // floats per stage = 8832
#define NN_SMEM (3 * STG_NN * 4)                // 105984 B

__global__ __launch_bounds__(256, 2)
void mm_nn(const float* __restrict__ A, const float* __restrict__ B, float* __restrict__ C,
           int M, int N, int K, int lda, int ldb, int ldc,
           const float* __restrict__ bias, int relu)
{
    extern __shared__ float sm_[];
    uint32_t sb = smem_u32(sm_);
    int t = threadIdx.x, wid = t >> 5, lane = t & 31, g = lane >> 2, q = lane & 3;
    int row0 = blockIdx.y * 128, col0 = blockIdx.x * 128;
    int wm = (wid >> 2) * 64, wn = (wid & 3) * 32;

    int lrow = t >> 1, lkc = (t & 1) * 16;       // A loader
    int krow = t >> 3, ncol = (t & 7) * 16;      // B loader
    const float* Ag = A + (size_t)(row0 + lrow) * lda + lkc;
    const float* Bg = B + (size_t)krow * ldb + col0 + ncol;
    uint32_t as_s = sb + (uint32_t)((lrow * AP + lkc) * 4);
    uint32_t bs_s = sb + (uint32_t)((128 * AP + krow * BP_NN + ncol) * 4);

    float acc[4][4][4];
    #pragma unroll
    for (int i = 0; i < 4; i++)
        #pragma unroll
        for (int j = 0; j < 4; j++)
            #pragma unroll
            for (int v = 0; v < 4; v++) acc[i][j][v] = 0.f;

    int NC = K >> 5;
    auto issue = [&](int c) {
        uint32_t off = (uint32_t)(c % 3) * STG_NN * 4;
        const float* ag = Ag + c * 32;
        const float* bg = Bg + (size_t)c * 32 * ldb;
        #pragma unroll
        for (int i = 0; i < 4; i++) cpa16(as_s + off + i * 16, ag + i * 4);
        #pragma unroll
        for (int i = 0; i < 4; i++) cpa16(bs_s + off + i * 16, bg + i * 4);
        cpcommit();
    };
    issue(0);
    if (NC > 1) issue(1);

    for (int c = 0; c < NC; c++) {
        if (c + 1 < NC) asm volatile("cp.async.wait_group 1;" ::: "memory");
        else            asm volatile("cp.async.wait_group 0;" ::: "memory");
        __syncthreads();
        if (c + 2 < NC) issue(c + 2);

        const float* As = sm_ + (c % 3) * STG_NN;
        const float* Bs = As + 128 * AP;
        #pragma unroll
        for (int ks = 0; ks < 32; ks += 8) {
            uint32_t af[4][4], bf[4][2];
            #pragma unroll
            for (int mt = 0; mt < 4; mt++) {
                int r = wm + mt * 16 + g;
                af[mt][0] = tf32u(As[r * AP + ks + q]);
                af[mt][1] = tf32u(As[(r + 8) * AP + ks + q]);
                af[mt][2] = tf32u(As[r * AP + ks + q + 4]);
                af[mt][3] = tf32u(As[(r + 8) * AP + ks + q + 4]);
            }
            #pragma unroll
            for (int nt = 0; nt < 4; nt++) {
                int n = wn + nt * 8 + g;
                bf[nt][0] = tf32u(Bs[(ks + q) * BP_NN + n]);
                bf[nt][1] = tf32u(Bs[(ks + q + 4) * BP_NN + n]);
            }
            #pragma unroll
            for (int mt = 0; mt < 4; mt++)
                #pragma unroll
                for (int nt = 0; nt < 4; nt++)
                    mma_tf32(acc[mt][nt], af[mt], bf[nt]);
        }
    }

    #pragma unroll
    for (int mt = 0; mt < 4; mt++) {
        int row = row0 + wm + mt * 16 + g;
        #pragma unroll
        for (int nt = 0; nt < 4; nt++) {
            int col = col0 + wn + nt * 8 + q * 2;
            float b0 = bias ? bias[col] : 0.f;
            float b1 = bias ? bias[col + 1] : 0.f;
            float o0 = acc[mt][nt][0] + b0, o1 = acc[mt][nt][1] + b1;
            float o2 = acc[mt][nt][2] + b0, o3 = acc[mt][nt][3] + b1;
            if (relu) {
                o0 = fmaxf(o0, 0.f); o1 = fmaxf(o1, 0.f);
                o2 = fmaxf(o2, 0.f); o3 = fmaxf(o3, 0.f);
            }
            *(float2*)&C[(size_t)row * ldc + col]       = make_float2(o0, o1);
            *(float2*)&C[(size_t)(row + 8) * ldc + col] = make_float2(o2, o3);
        }
    }
}

// ============ mm_nt: C[M,N] = A[M,K] @ B[N,K]^T, batched over z=(b,h); BD ============
// A offset: z * sAz. B offset: (z & 15) * sBh  (per-HEAD slice of rh). C offset: z * sCz.
#define STG_NT (2 * 128 * AP)                    // 9216 floats
#define NT_SMEM (3 * STG_NT * 4)                 // 110592 B

__global__ __launch_bounds__(256, 2)
void mm_nt(const float* __restrict__ A, const float* __restrict__ B, float* __restrict__ C,
           int M, int N, int K, int lda, int ldb, int ldc,
           long sAz, long sBh, long sCz, int skipSum)
{
    int row0 = blockIdx.y * 128, col0 = blockIdx.x * 128;
    if (skipSum && row0 + col0 < skipSum) return;   // dead BD tiles
    extern __shared__ float sm_[];
    uint32_t sb = smem_u32(sm_);
    int t = threadIdx.x, wid = t >> 5, lane = t & 31, g = lane >> 2, q = lane & 3;
    int z = blockIdx.z;
    const float* Az = A + (size_t)z * sAz;
    const float* Bz = B + (size_t)(z & 15) * sBh;   // head offset (FIX: was z*0)
    float* Cz = C + (size_t)z * sCz;
    int wm = (wid >> 2) * 64, wn = (wid & 3) * 32;

    int lrow = t >> 1, lkc = (t & 1) * 16;
    const float* Ag = Az + (size_t)(row0 + lrow) * lda + lkc;
    const float* Bg = Bz + (size_t)(col0 + lrow) * ldb + lkc;
    uint32_t as_s = sb + (uint32_t)((lrow * AP + lkc) * 4);
    uint32_t bs_s = as_s + 128 * AP * 4;

    float acc[4][4][4];
    #pragma unroll
    for (int i = 0; i < 4; i++)
        #pragma unroll
        for (int j = 0; j < 4; j++)
            #pragma unroll
            for (int v = 0; v < 4; v++) acc[i][j][v] = 0.f;

    int NC = K >> 5;
    auto issue = [&](int c) {
        uint32_t off = (uint32_t)(c % 3) * STG_NT * 4;
        const float* ag = Ag + c * 32;
        const float* bg = Bg + c * 32;
        #pragma unroll
        for (int i = 0; i < 4; i++) cpa16(as_s + off + i * 16, ag + i * 4);
        #pragma unroll
        for (int i = 0; i < 4; i++) cpa16(bs_s + off + i * 16, bg + i * 4);
        cpcommit();
    };
    issue(0);
    if (NC > 1) issue(1);

    for (int c = 0; c < NC; c++) {
        if (c + 1 < NC) asm volatile("cp.async.wait_group 1;" ::: "memory");
        else            asm volatile("cp.async.wait_group 0;" ::: "memory");
        __syncthreads();
        if (c + 2 < NC) issue(c + 2);

        const float* As = sm_ + (c % 3) * STG_NT;
        const float* Bs = As + 128 * AP;
        #pragma unroll
        for (int ks = 0; ks < 32; ks += 8) {
            uint32_t af[4][4], bf[4][2];
            #pragma unroll
            for (int mt = 0; mt < 4; mt++) {
                int r = wm + mt * 16 + g;
                af[mt][0] = tf32u(As[r * AP + ks + q]);
                af[mt][1] = tf32u(As[(r + 8) * AP + ks + q]);
                af[mt][2] = tf32u(As[r * AP + ks + q + 4]);
                af[mt][3] = tf32u(As[(r + 8) * AP + ks + q + 4]);
            }
            #pragma unroll
            for (int nt = 0; nt < 4; nt++) {
                int rn = wn + nt * 8 + g;
                bf[nt][0] = tf32u(Bs[rn * AP + ks + q]);
                bf[nt][1] = tf32u(Bs[rn * AP + ks + q + 4]);
            }
            #pragma unroll
            for (int mt = 0; mt < 4; mt++)
                #pragma unroll
                for (int nt = 0; nt < 4; nt++)
                    mma_tf32(acc[mt][nt], af[mt], bf[nt]);
        }
    }

    #pragma unroll
    for (int mt = 0; mt < 4; mt++) {
        int row = row0 + wm + mt * 16 + g;
        #pragma unroll
        for (int nt = 0; nt < 4; nt++) {
            int col = col0 + wn + nt * 8 + q * 2;
            *(float2*)&Cz[(size_t)row * ldc + col] =
                make_float2(acc[mt][nt][0], acc[mt][nt][1]);
            *(float2*)&Cz[(size_t)(row + 8) * ldc + col] =
                make_float2(acc[mt][nt][2], acc[mt][nt][3]);
        }
    }
}

// ============ AC GEMM + fused BD-shift + mask + exp + rowsum ============
__global__ __launch_bounds__(256, 2)
void ac_fused(const float* __restrict__ Qu, const float* __restrict__ qkv,
              const float* __restrict__ BD, float* __restrict__ S,
              float* __restrict__ rsum)
{
    int i0 = blockIdx.y * 128, j0 = blockIdx.x * 128;
    if (j0 > i0 + 639) return;
    extern __shared__ float sm_[];
    uint32_t sb = smem_u32(sm_);
    int t = threadIdx.x, wid = t >> 5, lane = t & 31, g = lane >> 2, q = lane & 3;
    int z = blockIdx.z, bb = z >> 4, hh = z & 15;
    int wm = (wid >> 2) * 64, wn = (wid & 3) * 32;

    int lrow = t >> 1, lkc = (t & 1) * 16;
    const float* Ag = Qu + (size_t)z * QLEN * HDIM + (size_t)(i0 + lrow) * HDIM + lkc;
    const float* Bg = qkv + ((size_t)(j0 + lrow) * 4 + bb) * 3072 + 1024 + hh * 64 + lkc;
    uint32_t as_s = sb + (uint32_t)((lrow * AP + lkc) * 4);
    uint32_t bs_s = as_s + 128 * AP * 4;

    float acc[4][4][4];
    #pragma unroll
    for (int i = 0; i < 4; i++)
        #pragma unroll
        for (int j = 0; j < 4; j++)
            #pragma unroll
            for (int v = 0; v < 4; v++) acc[i][j][v] = 0.f;

    auto issue = [&](int c) {
        uint32_t off = (uint32_t)(c % 3) * STG_NT * 4;
        const float* ag = Ag + c * 32;
        const float* bg = Bg + c * 32;
        #pragma unroll
        for (int i = 0; i < 4; i++) cpa16(as_s + off + i * 16, ag + i * 4);
        #pragma unroll
        for (int i = 0; i < 4; i++) cpa16(bs_s + off + i * 16, bg + i * 4);
        cpcommit();
    };
    issue(0); issue(1);

    #pragma unroll
    for (int c = 0; c < 2; c++) {                 // K=64, two chunks of 32
        if (c == 0) asm volatile("cp.async.wait_group 1;" ::: "memory");
        else        asm volatile("cp.async.wait_group 0;" ::: "memory");
        __syncthreads();

        const float* As = sm_ + c * STG_NT;
        const float* Bs = As + 128 * AP;
        #pragma unroll
        for (int ks = 0; ks < 32; ks += 8) {
            uint32_t af[4][4], bf[4][2];
            #pragma unroll
            for (int mt = 0; mt < 4; mt++) {
                int r = wm + mt * 16 + g;
                af[mt][0] = tf32u(As[r * AP + ks + q]);
                af[mt][1] = tf32u(As[(r + 8) * AP + ks + q]);
                af[mt][2] = tf32u(As[r * AP + ks + q + 4]);
                af[mt][3] = tf32u(As[(r + 8) * AP + ks + q + 4]);
            }
            #pragma unroll
            for (int nt = 0; nt < 4; nt++) {
                int rn = wn + nt * 8 + g;
                bf[nt][0] = tf32u(Bs[rn * AP + ks + q]);
                bf[nt][1] = tf32u(Bs[rn * AP + ks + q + 4]);
            }
            #pragma unroll
            for (int mt = 0; mt < 4; mt++)
                #pragma unroll
                for (int nt = 0; nt < 4; nt++)
                    mma_tf32(acc[mt][nt], af[mt], bf[nt]);
        }
    }

    const float* BDz = BD + (size_t)z * QLEN * KLENC;
    float* Sz = S + (size_t)z * QLEN * KLENC;
    float* rz = rsum + (size_t)z * QLEN;
    #pragma unroll
    for (int mt = 0; mt < 4; mt++) {
        int r0i = i0 + wm + mt * 16 + g;
        int r1i = r0i + 8;
        float s0 = 0.f, s1 = 0.f;
        const float* bd0 = BDz + (size_t)r0i * KLENC + (1023 - r0i);
        const float* bd1 = BDz + (size_t)r1i * KLENC + (1023 - r1i);
        #pragma unroll
        for (int nt = 0; nt < 4; nt++) {
            int col = j0 + wn + nt * 8 + q * 2;
            int v00 = (col     <= r0i + 512);
            int v01 = (col + 1 <= r0i + 512);
            int v10 = (col     <= r1i + 512);
            int v11 = (col + 1 <= r1i + 512);
            float p00 = v00 ? __expf((acc[mt][nt][0] + bd0[col])     * ATT_SCALE) : 0.f;
            float p01 = v01 ? __expf((acc[mt][nt][1] + bd0[col + 1]) * ATT_SCALE) : 0.f;
            float p10 = v10 ? __expf((acc[mt][nt][2] + bd1[col])     * ATT_SCALE) : 0.f;
            float p11 = v11 ? __expf((acc[mt][nt][3] + bd1[col + 1]) * ATT_SCALE) : 0.f;
            s0 += p00 + p01;
            s1 += p10 + p11;
            *(float2*)&Sz[(size_t)r0i * KLENC + col] = make_float2(p00, p01);
            *(float2*)&Sz[(size_t)r1i * KLENC + col] = make_float2(p10, p11);
        }
        s0 += __shfl_xor_sync(0xffffffffu, s0, 1);
        s0 += __shfl_xor_sync(0xffffffffu, s0, 2);
        s1 += __shfl_xor_sync(0xffffffffu, s1, 1);
        s1 += __shfl_xor_sync(0xffffffffu, s1, 2);
        if (q == 0) {
            atomicAdd(&rz[r0i], s0);
            atomicAdd(&rz[r1i], s1);
        }
    }
}

// ============ PV: ctx = (P @ V) / rsum ============
#define VPV 72
#define STG_PV (128 * AP + 32 * VPV)             // 6912 floats
#define PV_SMEM (3 * STG_PV * 4)                 // 82944 B

__global__ __launch_bounds__(256, 2)
void pv_mma(const float* __restrict__ S, const float* __restrict__ qkv,
            const float* __restrict__ rsum, float* __restrict__ ctx)
{
    extern __shared__ float sm_[];
    uint32_t sb = smem_u32(sm_);
    int t = threadIdx.x, wid = t >> 5, lane = t & 31, g = lane >> 2, q = lane & 3;
    int i0 = blockIdx.x * 128;
    int z = blockIdx.y, bb = z >> 4, hh = z & 15;
    int wm = (wid >> 1) * 32, wn = (wid & 1) * 32;

    int lrow = t >> 1, lkc = (t & 1) * 16;
    const float* Ag = S + ((size_t)z * QLEN + i0 + lrow) * KLENC + lkc;
    uint32_t as_s = sb + (uint32_t)((lrow * AP + lkc) * 4);
    int krow = t >> 3, vcol = (t & 7) * 8;
    uint32_t vs_s = sb + (uint32_t)((128 * AP + krow * VPV + vcol) * 4);

    float acc[2][4][4];
    #pragma unroll
    for (int i = 0; i < 2; i++)
        #pragma unroll
        for (int j = 0; j < 4; j++)
            #pragma unroll
            for (int v = 0; v < 4; v++) acc[i][j][v] = 0.f;

    int jlim = i0 + 640; if (jlim > KLENC) jlim = KLENC;
    int NC = jlim >> 5;

    auto issue = [&](int c) {
        uint32_t off = (uint32_t)(c % 3) * STG_PV * 4;
        const float* ag = Ag + c * 32;
        #pragma unroll
        for (int i = 0; i < 4; i++) cpa16(as_s + off + i * 16, ag + i * 4);
        const float* vg = qkv + ((size_t)((c * 32 + krow) * 4 + bb)) * 3072 + 2048 + hh * 64 + vcol;
        cpa16(vs_s + off, vg); cpa16(vs_s + off + 16, vg + 4);
        cpcommit();
    };
    issue(0);
    if (NC > 1) issue(1);

    for (int c = 0; c < NC; c++) {
        if (c + 1 < NC) asm volatile("cp.async.wait_group 1;" ::: "memory");
        else            asm volatile("cp.async.wait_group 0;" ::: "memory");
        __syncthreads();
        if (c + 2 < NC) issue(c + 2);

        const float* As = sm_ + (c % 3) * STG_PV;
        const float* Vs = As + 128 * AP;
        #pragma unroll
        for (int ks = 0; ks < 32; ks += 8) {
            uint32_t af[2][4], bf[4][2];
            #pragma unroll
            for (int mt = 0; mt < 2; mt++) {
                int r = wm + mt * 16 + g;
                af[mt][0] = tf32u(As[r * AP + ks + q]);
                af[mt][1] = tf32u(As[(r + 8) * AP + ks + q]);
                af[mt][2] = tf32u(As[r * AP + ks + q + 4]);
                af[mt][3] = tf32u(As[(r + 8) * AP + ks + q + 4]);
            }
            #pragma unroll
            for (int nt = 0; nt < 4; nt++) {
                int n = wn + nt * 8 + g;
                bf[nt][0] = tf32u(Vs[(ks + q) * VPV + n]);
                bf[nt][1] = tf32u(Vs[(ks + q + 4) * VPV + n]);
            }
            #pragma unroll
            for (int mt = 0; mt < 2; mt++)
                #pragma unroll
                for (int nt = 0; nt < 4; nt++)
                    mma_tf32(acc[mt][nt], af[mt], bf[nt]);
        }
    }

    const float* rz = rsum + (size_t)z * QLEN;
    #pragma unroll
    for (int mt = 0; mt < 2; mt++) {
        int m = i0 + wm + mt * 16 + g;
        float inv0 = 1.f / rz[m];
        float inv1 = 1.f / rz[m + 8];
        #pragma unroll
        for (int nt = 0; nt < 4; nt++) {
            int d = wn + nt * 8 + q * 2;
            size_t o0 = ((size_t)m * 4 + bb) * 1024 + hh * 64 + d;
            size_t o1 = ((size_t)(m + 8) * 4 + bb) * 1024 + hh * 64 + d;
            *(float2*)&ctx[o0] = make_float2(acc[mt][nt][0] * inv0, acc[mt][nt][1] * inv0);
            *(float2*)&ctx[o1] = make_float2(acc[mt][nt][2] * inv1, acc[mt][nt][3] * inv1);
        }
    }
}

// ---------------- Qu/Qv prep ----------------
__global__ void quv_prep(const float* __restrict__ qkv, const float* __restrict__ u,
                         const float* __restrict__ v, float* __restrict__ Qu,
                         float* __restrict__ Qv)
{
    size_t idx = (size_t)blockIdx.x * 256 + threadIdx.x;
    int d = idx & 63;
    size_t row = idx >> 6;
    int i = row & 1023;
    int z = row >> 10, bb = z >> 4, hh = z & 15;
    float qv = qkv[((size_t)((MEMLEN + i) * 4 + bb)) * 3072 + hh * 64 + d];
    Qu[idx] = qv + u[hh * 64 + d];
    Qv[idx] = qv + v[hh * 64 + d];
}

// ---------------- layernorm ----------------
__device__ __forceinline__ float block_sum256(float v, float* red)
{
    #pragma unroll
    for (int o = 16; o; o >>= 1) v += __shfl_xor_sync(0xffffffffu, v, o);
    if ((threadIdx.x & 31) == 0) red[threadIdx.x >> 5] = v;
    __syncthreads();
    float s = 0.f;
    #pragma unroll
    for (int w = 0; w < 8; w++) s += red[w];
    __syncthreads();
    return s;
}

__global__ void ln_kernel(const float* __restrict__ A, const float* __restrict__ Bv,
                          const float* __restrict__ g, const float* __restrict__ be,
                          float* __restrict__ out)
{
    int row = blockIdx.x;
    int t = threadIdx.x;
    __shared__ float red[8];
    size_t base = (size_t)row * DMODEL;

    float x[4];
    float s = 0.f;
    #pragma unroll
    for (int r = 0; r < 4; r++) {
        int c = t + r * 256;
        x[r] = A[base + c] + Bv[base + c];
        s += x[r];
    }
    float mean = block_sum256(s, red) * (1.f / DMODEL);

    float q = 0.f;
    #pragma unroll
    for (int r = 0; r < 4; r++) {
        float d = x[r] - mean;
        q += d * d;
    }
    float var = block_sum256(q, red) * (1.f / DMODEL);
    float rstd = rsqrtf(var + 1e-5f);

    #pragma unroll
    for (int r = 0; r < 4; r++) {
        int c = t + r * 256;
        out[base + c] = (x[r] - mean) * rstd * g[c] + be[c];
    }
}

// ---------------- host orchestration ----------------
extern "C" void kernel_launch(void* const* d_in, const int* in_sizes, int n_in,
                              void* d_out, int out_size)
{
    (void)in_sizes; (void)out_size;
    int off = (n_in >= 17) ? 0 : -1;
    const float* inp   = (const float*)d_in[0];
    const float* r     = (const float*)d_in[1];
    const float* u     = (const float*)d_in[2];
    const float* v     = (const float*)d_in[3];
    const float* mem   = (const float*)d_in[4];
    const float* W_qkv = (const float*)d_in[6 + off];
    const float* W_r   = (const float*)d_in[7 + off];
    const float* W_o   = (const float*)d_in[8 + off];
    const float* ln1g  = (const float*)d_in[9 + off];
    const float* ln1b  = (const float*)d_in[10 + off];
    const float* ln2g  = (const float*)d_in[11 + off];
    const float* ln2b  = (const float*)d_in[12 + off];
    const float* W1    = (const float*)d_in[13 + off];
    const float* b1    = (const float*)d_in[14 + off];
    const float* W2    = (const float*)d_in[15 + off];
    const float* b2    = (const float*)d_in[16 + off];
    float* out = (float*)d_out;

    float *cat_p, *qkv_p, *rh_p, *S_p, *BD_p, *Qu_p, *Qv_p, *rs_p, *ctx_p, *y_p, *x_p, *h_p, *y2_p;
    cudaGetSymbolAddress((void**)&cat_p, g_cat);
    cudaGetSymbolAddress((void**)&qkv_p, g_qkv);
    cudaGetSymbolAddress((void**)&rh_p,  g_rh);
    cudaGetSymbolAddress((void**)&S_p,   g_S);
    cudaGetSymbolAddress((void**)&BD_p,  g_BD);
    cudaGetSymbolAddress((void**)&Qu_p,  g_Qu);
    cudaGetSymbolAddress((void**)&Qv_p,  g_Qv);
    cudaGetSymbolAddress((void**)&rs_p,  g_rsum);
    cudaGetSymbolAddress((void**)&ctx_p, g_ctx);
    cudaGetSymbolAddress((void**)&y_p,   g_y);
    cudaGetSymbolAddress((void**)&x_p,   g_x);
    cudaGetSymbolAddress((void**)&h_p,   g_h);
    cudaGetSymbolAddress((void**)&y2_p,  g_y2);

    cudaFuncSetAttribute(mm_nn,   cudaFuncAttributeMaxDynamicSharedMemorySize, NN_SMEM);
    cudaFuncSetAttribute(mm_nt,   cudaFuncAttributeMaxDynamicSharedMemorySize, NT_SMEM);
    cudaFuncSetAttribute(ac_fused, cudaFuncAttributeMaxDynamicSharedMemorySize, NT_SMEM);
    cudaFuncSetAttribute(pv_mma,  cudaFuncAttributeMaxDynamicSharedMemorySize, PV_SMEM);

    // cat = [mem; inputs]
    cudaMemcpyAsync(cat_p, mem, (size_t)MEMLEN * BATCH * DMODEL * sizeof(float),
                    cudaMemcpyDeviceToDevice);
    cudaMemcpyAsync(cat_p + (size_t)MEMLEN * BATCH * DMODEL, inp,
                    (size_t)QLEN * BATCH * DMODEL * sizeof(float),
                    cudaMemcpyDeviceToDevice);
    cudaMemsetAsync(rs_p, 0, (size_t)64 * QLEN * sizeof(float));

    dim3 blk(256);
    // qkv = cat @ W_qkv  (W in [K,N] directly — no transpose)
    mm_nn<<<dim3(3072/128, 6144/128), blk, NN_SMEM>>>(
        cat_p, W_qkv, qkv_p, 6144, 3072, 1024, 1024, 3072, 3072, nullptr, 0);
    // r_h = r @ W_r
    mm_nn<<<dim3(1024/128, 1536/128), blk, NN_SMEM>>>(
        r, W_r, rh_p, 1536, 1024, 1024, 1024, 1024, 1024, nullptr, 0);
    // Qu/Qv prep
    quv_prep<<<(64 * QLEN * HDIM) / 256, 256>>>(qkv_p, u, v, Qu_p, Qv_p);
    // BD[z] = Qv @ rh[:, h*64:h*64+64]^T, dead tiles skipped
    mm_nt<<<dim3(1536/128, 1024/128, 64), blk, NT_SMEM>>>(
        Qv_p, rh_p, BD_p, 1024, 1536, 64, 64, 1024, 1536,
        (long)1024*64, 64, (long)1024*1536, 769);
    // P = exp(mask(AC + shift(BD)) * scale), rowsum -> rsum
    ac_fused<<<dim3(1536/128, 1024/128, 64), blk, NT_SMEM>>>(
        Qu_p, qkv_p, BD_p, S_p, rs_p);
    // ctx = (P @ V) / rsum
    pv_mma<<<dim3(QLEN/128, 64), blk, PV_SMEM>>>(S_p, qkv_p, rs_p, ctx_p);
    // y = ctx @ W_o
    mm_nn<<<dim3(1024/128, 4096/128), blk, NN_SMEM>>>(
        ctx_p, W_o, y_p, 4096, 1024, 1024, 1024, 1024, 1024, nullptr, 0);
    ln_kernel<<<NROWS, 256>>>(inp, y_p, ln1g, ln1b, x_p);
    // h = relu(x @ W1 + b1)
    mm_nn<<<dim3(4096/128, 4096/128), blk, NN_SMEM>>>(
        x_p, W1, h_p, 4096, 4096, 1024, 1024, 4096, 4096, b1, 1);
    // y2 = h @ W2 + b2
    mm_nn<<<dim3(1024/128, 4096/128), blk, NN_SMEM>>>(
        h_p, W2, y2_p, 4096, 1024, 4096, 4096, 1024, 1024, b2, 0);
    ln_kernel<<<NROWS, 256>>>(x_p, y2_p, ln2g, ln2b, out);
}

// round 10
// speedup vs baseline: 1.1775x; 1.1775x over previous
#include <cuda_runtime.h>
#include <cstdint>
#include <math.h>

// ---------------- problem constants ----------------
#define QLEN    1024
#define BATCH   4
#define DMODEL  1024
#define NHEAD   16
#define HDIM    64
#define MEMLEN  512
#define KLENC   1536
#define MLPD    4096
#define ATT_SCALE 0.125f
#define NROWS   4096
#define KROWS   6144

// ---------------- scratch ----------------
__device__ __align__(16) float g_cat[(size_t)KROWS * DMODEL];
__device__ __align__(16) float g_qkv[(size_t)KROWS * 3 * DMODEL];
__device__ __align__(16) float g_rh [(size_t)KLENC * DMODEL];
__device__ __align__(16) float g_S  [(size_t)64 * QLEN * KLENC];
__device__ __align__(16) float g_BD [(size_t)64 * QLEN * KLENC];
__device__ __align__(16) float g_Qu [(size_t)64 * QLEN * HDIM];
__device__ __align__(16) float g_Qv [(size_t)64 * QLEN * HDIM];
__device__ __align__(16) float g_rsum[(size_t)64 * QLEN];
__device__ __align__(16) float g_ctx[(size_t)NROWS * DMODEL];
__device__ __align__(16) float g_y  [(size_t)NROWS * DMODEL];
__device__ __align__(16) float g_x  [(size_t)NROWS * DMODEL];
__device__ __align__(16) float g_h  [(size_t)NROWS * MLPD];
__device__ __align__(16) float g_y2 [(size_t)NROWS * DMODEL];

// ---------------- helpers ----------------
__device__ __forceinline__ uint32_t smem_u32(const void* p) {
    uint32_t a;
    asm("{ .reg .u64 t; cvta.to.shared.u64 t, %1; cvt.u32.u64 %0, t; }" : "=r"(a) : "l"(p));
    return a;
}
__device__ __forceinline__ uint32_t tf32u(float x) {
    uint32_t u;
    asm("cvt.rna.tf32.f32 %0, %1;" : "=r"(u) : "f"(x));
    return u;
}
__device__ __forceinline__ void cpa16(uint32_t s, const void* g) {
    asm volatile("cp.async.cg.shared.global [%0], [%1], 16;" :: "r"(s), "l"(g));
}
__device__ __forceinline__ void cpcommit() {
    asm volatile("cp.async.commit_group;" ::: "memory");
}
__device__ __forceinline__ void mma_tf32(float* c, const uint32_t* a, const uint32_t* b)
{
    asm volatile(
        "mma.sync.aligned.m16n8k8.row.col.f32.tf32.tf32.f32 "
        "{%0,%1,%2,%3}, {%4,%5,%6,%7}, {%8,%9}, {%0,%1,%2,%3};"
        : "+f"(c[0]), "+f"(c[1]), "+f"(c[2]), "+f"(c[3])
        : "r"(a[0]), "r"(a[1]), "r"(a[2]), "r"(a[3]), "r"(b[0]), "r"(b[1]));
}

// K-chunk = 16 everywhere (occupancy-friendly: stage <= ~20KB, 3-stage ring).
#define SMP 20          // A tile pitch: [128][20]
#define BPN 136         // NN B tile pitch: [16][136]; 136 % 32 == 8 -> conflict-free frags

// ============ mm_nn: C[M,N] = A[M,K] @ B[K,N], B row-major [K,N] ============
#define STG_NN (128 * SMP + 16 * BPN)           // 4736 floats/stage
#define NN_SMEM (3 * STG_NN * 4)                // 56832 B

__global__ __launch_bounds__(256, 2)
void mm_nn(const float* __restrict__ A, const float* __restrict__ B, float* __restrict__ C,
           int M, int N, int K, int lda, int ldb, int ldc,
           const float* __restrict__ bias, int relu)
{
    extern __shared__ float sm_[];
    uint32_t sb = smem_u32(sm_);
    int t = threadIdx.x, wid = t >> 5, lane = t & 31, g = lane >> 2, q = lane & 3;
    int row0 = blockIdx.y * 128, col0 = blockIdx.x * 128;
    int wm = (wid >> 2) * 64, wn = (wid & 3) * 32;

    int lrow = t >> 1, lkc = (t & 1) * 8;        // A loader: 8 floats/thread
    int krow = t >> 4, ncol = (t & 15) * 8;      // B loader: 8 floats/thread
    const float* Ag = A + (size_t)(row0 + lrow) * lda + lkc;
    const float* Bg = B + (size_t)krow * ldb + col0 + ncol;
    uint32_t as_s = sb + (uint32_t)((lrow * SMP + lkc) * 4);
    uint32_t bs_s = sb + (uint32_t)((128 * SMP + krow * BPN + ncol) * 4);

    float acc[4][4][4];
    #pragma unroll
    for (int i = 0; i < 4; i++)
        #pragma unroll
        for (int j = 0; j < 4; j++)
            #pragma unroll
            for (int v = 0; v < 4; v++) acc[i][j][v] = 0.f;

    int NC = K >> 4;
    auto issue = [&](int c) {
        uint32_t off = (uint32_t)(c % 3) * STG_NN * 4;
        const float* ag = Ag + c * 16;
        const float* bg = Bg + (size_t)c * 16 * ldb;
        cpa16(as_s + off, ag);       cpa16(as_s + off + 16, ag + 4);
        cpa16(bs_s + off, bg);       cpa16(bs_s + off + 16, bg + 4);
        cpcommit();
    };
    issue(0);
    if (NC > 1) issue(1);

    for (int c = 0; c < NC; c++) {
        if (c + 1 < NC) asm volatile("cp.async.wait_group 1;" ::: "memory");
        else            asm volatile("cp.async.wait_group 0;" ::: "memory");
        __syncthreads();
        if (c + 2 < NC) issue(c + 2);

        const float* As = sm_ + (c % 3) * STG_NN;
        const float* Bs = As + 128 * SMP;
        #pragma unroll
        for (int ks = 0; ks < 16; ks += 8) {
            uint32_t af[4][4], bf[4][2];
            #pragma unroll
            for (int mt = 0; mt < 4; mt++) {
                int r = wm + mt * 16 + g;
                af[mt][0] = tf32u(As[r * SMP + ks + q]);
                af[mt][1] = tf32u(As[(r + 8) * SMP + ks + q]);
                af[mt][2] = tf32u(As[r * SMP + ks + q + 4]);
                af[mt][3] = tf32u(As[(r + 8) * SMP + ks + q + 4]);
            }
            #pragma unroll
            for (int nt = 0; nt < 4; nt++) {
                int n = wn + nt * 8 + g;
                bf[nt][0] = tf32u(Bs[(ks + q) * BPN + n]);
                bf[nt][1] = tf32u(Bs[(ks + q + 4) * BPN + n]);
            }
            #pragma unroll
            for (int mt = 0; mt < 4; mt++)
                #pragma unroll
                for (int nt = 0; nt < 4; nt++)
                    mma_tf32(acc[mt][nt], af[mt], bf[nt]);
        }
    }

    #pragma unroll
    for (int mt = 0; mt < 4; mt++) {
        int row = row0 + wm + mt * 16 + g;
        #pragma unroll
        for (int nt = 0; nt < 4; nt++) {
            int col = col0 + wn + nt * 8 + q * 2;
            float b0 = bias ? bias[col] : 0.f;
            float b1 = bias ? bias[col + 1] : 0.f;
            float o0 = acc[mt][nt][0] + b0, o1 = acc[mt][nt][1] + b1;
            float o2 = acc[mt][nt][2] + b0, o3 = acc[mt][nt][3] + b1;
            if (relu) {
                o0 = fmaxf(o0, 0.f); o1 = fmaxf(o1, 0.f);
                o2 = fmaxf(o2, 0.f); o3 = fmaxf(o3, 0.f);
            }
            *(float2*)&C[(size_t)row * ldc + col]       = make_float2(o0, o1);
            *(float2*)&C[(size_t)(row + 8) * ldc + col] = make_float2(o2, o3);
        }
    }
}

// ============ mm_nt: C = A @ B^T, batched over z=(b,h); used for BD ============
// A offset z*sAz; B offset (z&15)*sBh (per-head slice of rh); C offset z*sCz.
#define STG_NT (2 * 128 * SMP)                   // 5120 floats/stage
#define NT_SMEM (3 * STG_NT * 4)                 // 61440 B

__global__ __launch_bounds__(256, 2)
void mm_nt(const float* __restrict__ A, const float* __restrict__ B, float* __restrict__ C,
           int M, int N, int K, int lda, int ldb, int ldc,
           long sAz, long sBh, long sCz, int skipSum)
{
    int row0 = blockIdx.y * 128, col0 = blockIdx.x * 128;
    if (skipSum && row0 + col0 < skipSum) return;
    extern __shared__ float sm_[];
    uint32_t sb = smem_u32(sm_);
    int t = threadIdx.x, wid = t >> 5, lane = t & 31, g = lane >> 2, q = lane & 3;
    int z = blockIdx.z;
    const float* Az = A + (size_t)z * sAz;
    const float* Bz = B + (size_t)(z & 15) * sBh;
    float* Cz = C + (size_t)z * sCz;
    int wm = (wid >> 2) * 64, wn = (wid & 3) * 32;

    int lrow = t >> 1, lkc = (t & 1) * 8;
    const float* Ag = Az + (size_t)(row0 + lrow) * lda + lkc;
    const float* Bg = Bz + (size_t)(col0 + lrow) * ldb + lkc;
    uint32_t as_s = sb + (uint32_t)((lrow * SMP + lkc) * 4);
    uint32_t bs_s = as_s + 128 * SMP * 4;

    float acc[4][4][4];
    #pragma unroll
    for (int i = 0; i < 4; i++)
        #pragma unroll
        for (int j = 0; j < 4; j++)
            #pragma unroll
            for (int v = 0; v < 4; v++) acc[i][j][v] = 0.f;

    int NC = K >> 4;
    auto issue = [&](int c) {
        uint32_t off = (uint32_t)(c % 3) * STG_NT * 4;
        const float* ag = Ag + c * 16;
        const float* bg = Bg + c * 16;
        cpa16(as_s + off, ag); cpa16(as_s + off + 16, ag + 4);
        cpa16(bs_s + off, bg); cpa16(bs_s + off + 16, bg + 4);
        cpcommit();
    };
    issue(0);
    if (NC > 1) issue(1);

    for (int c = 0; c < NC; c++) {
        if (c + 1 < NC) asm volatile("cp.async.wait_group 1;" ::: "memory");
        else            asm volatile("cp.async.wait_group 0;" ::: "memory");
        __syncthreads();
        if (c + 2 < NC) issue(c + 2);

        const float* As = sm_ + (c % 3) * STG_NT;
        const float* Bs = As + 128 * SMP;
        #pragma unroll
        for (int ks = 0; ks < 16; ks += 8) {
            uint32_t af[4][4], bf[4][2];
            #pragma unroll
            for (int mt = 0; mt < 4; mt++) {
                int r = wm + mt * 16 + g;
                af[mt][0] = tf32u(As[r * SMP + ks + q]);
                af[mt][1] = tf32u(As[(r + 8) * SMP + ks + q]);
                af[mt][2] = tf32u(As[r * SMP + ks + q + 4]);
                af[mt][3] = tf32u(As[(r + 8) * SMP + ks + q + 4]);
            }
            #pragma unroll
            for (int nt = 0; nt < 4; nt++) {
                int rn = wn + nt * 8 + g;
                bf[nt][0] = tf32u(Bs[rn * SMP + ks + q]);
                bf[nt][1] = tf32u(Bs[rn * SMP + ks + q + 4]);
            }
            #pragma unroll
            for (int mt = 0; mt < 4; mt++)
                #pragma unroll
                for (int nt = 0; nt < 4; nt++)
                    mma_tf32(acc[mt][nt], af[mt], bf[nt]);
        }
    }

    #pragma unroll
    for (int mt = 0; mt < 4; mt++) {
        int row = row0 + wm + mt * 16 + g;
        #pragma unroll
        for (int nt = 0; nt < 4; nt++) {
            int col = col0 + wn + nt * 8 + q * 2;
            *(float2*)&Cz[(size_t)row * ldc + col] =
                make_float2(acc[mt][nt][0], acc[mt][nt][1]);
            *(float2*)&Cz[(size_t)(row + 8) * ldc + col] =
                make_float2(acc[mt][nt][2], acc[mt][nt][3]);
        }
    }
}

// ============ AC GEMM + fused BD-shift + mask + exp + rowsum ============
__global__ __launch_bounds__(256, 2)
void ac_fused(const float* __restrict__ Qu, const float* __restrict__ qkv,
              const float* __restrict__ BD, float* __restrict__ S,
              float* __restrict__ rsum)
{
    int i0 = blockIdx.y * 128, j0 = blockIdx.x * 128;
    if (j0 > i0 + 639) return;
    extern __shared__ float sm_[];
    uint32_t sb = smem_u32(sm_);
    int t = threadIdx.x, wid = t >> 5, lane = t & 31, g = lane >> 2, q = lane & 3;
    int z = blockIdx.z, bb = z >> 4, hh = z & 15;
    int wm = (wid >> 2) * 64, wn = (wid & 3) * 32;

    int lrow = t >> 1, lkc = (t & 1) * 8;
    const float* Ag = Qu + (size_t)z * QLEN * HDIM + (size_t)(i0 + lrow) * HDIM + lkc;
    const float* Bg = qkv + ((size_t)(j0 + lrow) * 4 + bb) * 3072 + 1024 + hh * 64 + lkc;
    uint32_t as_s = sb + (uint32_t)((lrow * SMP + lkc) * 4);
    uint32_t bs_s = as_s + 128 * SMP * 4;

    float acc[4][4][4];
    #pragma unroll
    for (int i = 0; i < 4; i++)
        #pragma unroll
        for (int j = 0; j < 4; j++)
            #pragma unroll
            for (int v = 0; v < 4; v++) acc[i][j][v] = 0.f;

    auto issue = [&](int c) {
        uint32_t off = (uint32_t)(c % 3) * STG_NT * 4;
        const float* ag = Ag + c * 16;
        const float* bg = Bg + c * 16;
        cpa16(as_s + off, ag); cpa16(as_s + off + 16, ag + 4);
        cpa16(bs_s + off, bg); cpa16(bs_s + off + 16, bg + 4);
        cpcommit();
    };
    issue(0); issue(1);

    #pragma unroll
    for (int c = 0; c < 4; c++) {                 // K=64, 4 chunks of 16
        if (c + 1 < 4) asm volatile("cp.async.wait_group 1;" ::: "memory");
        else           asm volatile("cp.async.wait_group 0;" ::: "memory");
        __syncthreads();
        if (c + 2 < 4) issue(c + 2);

        const float* As = sm_ + (c % 3) * STG_NT;
        const float* Bs = As + 128 * SMP;
        #pragma unroll
        for (int ks = 0; ks < 16; ks += 8) {
            uint32_t af[4][4], bf[4][2];
            #pragma unroll
            for (int mt = 0; mt < 4; mt++) {
                int r = wm + mt * 16 + g;
                af[mt][0] = tf32u(As[r * SMP + ks + q]);
                af[mt][1] = tf32u(As[(r + 8) * SMP + ks + q]);
                af[mt][2] = tf32u(As[r * SMP + ks + q + 4]);
                af[mt][3] = tf32u(As[(r + 8) * SMP + ks + q + 4]);
            }
            #pragma unroll
            for (int nt = 0; nt < 4; nt++) {
                int rn = wn + nt * 8 + g;
                bf[nt][0] = tf32u(Bs[rn * SMP + ks + q]);
                bf[nt][1] = tf32u(Bs[rn * SMP + ks + q + 4]);
            }
            #pragma unroll
            for (int mt = 0; mt < 4; mt++)
                #pragma unroll
                for (int nt = 0; nt < 4; nt++)
                    mma_tf32(acc[mt][nt], af[mt], bf[nt]);
        }
    }

    const float* BDz = BD + (size_t)z * QLEN * KLENC;
    float* Sz = S + (size_t)z * QLEN * KLENC;
    float* rz = rsum + (size_t)z * QLEN;
    #pragma unroll
    for (int mt = 0; mt < 4; mt++) {
        int r0i = i0 + wm + mt * 16 + g;
        int r1i = r0i + 8;
        float s0 = 0.f, s1 = 0.f;
        const float* bd0 = BDz + (size_t)r0i * KLENC + (1023 - r0i);
        const float* bd1 = BDz + (size_t)r1i * KLENC + (1023 - r1i);
        #pragma unroll
        for (int nt = 0; nt < 4; nt++) {
            int col = j0 + wn + nt * 8 + q * 2;
            int v00 = (col     <= r0i + 512);
            int v01 = (col + 1 <= r0i + 512);
            int v10 = (col     <= r1i + 512);
            int v11 = (col + 1 <= r1i + 512);
            float p00 = v00 ? __expf((acc[mt][nt][0] + bd0[col])     * ATT_SCALE) : 0.f;
            float p01 = v01 ? __expf((acc[mt][nt][1] + bd0[col + 1]) * ATT_SCALE) : 0.f;
            float p10 = v10 ? __expf((acc[mt][nt][2] + bd1[col])     * ATT_SCALE) : 0.f;
            float p11 = v11 ? __expf((acc[mt][nt][3] + bd1[col + 1]) * ATT_SCALE) : 0.f;
            s0 += p00 + p01;
            s1 += p10 + p11;
            *(float2*)&Sz[(size_t)r0i * KLENC + col] = make_float2(p00, p01);
            *(float2*)&Sz[(size_t)r1i * KLENC + col] = make_float2(p10, p11);
        }
        s0 += __shfl_xor_sync(0xffffffffu, s0, 1);
        s0 += __shfl_xor_sync(0xffffffffu, s0, 2);
        s1 += __shfl_xor_sync(0xffffffffu, s1, 1);
        s1 += __shfl_xor_sync(0xffffffffu, s1, 2);
        if (q == 0) {
            atomicAdd(&rz[r0i], s0);
            atomicAdd(&rz[r1i], s1);
        }
    }
}

// ============ PV: ctx = (P @ V) / rsum ============
#define VPV 72
#define STG_PV (128 * SMP + 16 * VPV)            // 3712 floats/stage
#define PV_SMEM (3 * STG_PV * 4)                 // 44544 B

__global__ __launch_bounds__(256, 2)
void pv_mma(const float* __restrict__ S, const float* __restrict__ qkv,
            const float* __restrict__ rsum, float* __restrict__ ctx)
{
    extern __shared__ float sm_[];
    uint32_t sb = smem_u32(sm_);
    int t = threadIdx.x, wid = t >> 5, lane = t & 31, g = lane >> 2, q = lane & 3;
    int i0 = blockIdx.x * 128;
    int z = blockIdx.y, bb = z >> 4, hh = z & 15;
    int wm = (wid >> 1) * 32, wn = (wid & 1) * 32;

    const float* Ag = S + ((size_t)z * QLEN + i0 + (t >> 1)) * KLENC + (t & 1) * 8;
    uint32_t as_s = sb + (uint32_t)(((t >> 1) * SMP + (t & 1) * 8) * 4);
    int vrow = (t & 127) >> 3, vcol = (t & 7) * 8;
    uint32_t vs_s = sb + (uint32_t)((128 * SMP + vrow * VPV + vcol) * 4);

    float acc[2][4][4];
    #pragma unroll
    for (int i = 0; i < 2; i++)
        #pragma unroll
        for (int j = 0; j < 4; j++)
            #pragma unroll
            for (int v = 0; v < 4; v++) acc[i][j][v] = 0.f;

    int jlim = i0 + 640; if (jlim > KLENC) jlim = KLENC;
    int NC = jlim >> 4;

    auto issue = [&](int c) {
        uint32_t off = (uint32_t)(c % 3) * STG_PV * 4;
        const float* ag = Ag + c * 16;
        cpa16(as_s + off, ag); cpa16(as_s + off + 16, ag + 4);
        if (t < 128) {
            const float* vg = qkv + ((size_t)((c * 16 + vrow) * 4 + bb)) * 3072 + 2048 + hh * 64 + vcol;
            cpa16(vs_s + off, vg); cpa16(vs_s + off + 16, vg + 4);
        }
        cpcommit();
    };
    issue(0);
    if (NC > 1) issue(1);

    for (int c = 0; c < NC; c++) {
        if (c + 1 < NC) asm volatile("cp.async.wait_group 1;" ::: "memory");
        else            asm volatile("cp.async.wait_group 0;" ::: "memory");
        __syncthreads();
        if (c + 2 < NC) issue(c + 2);

        const float* As = sm_ + (c % 3) * STG_PV;
        const float* Vs = As + 128 * SMP;
        #pragma unroll
        for (int ks = 0; ks < 16; ks += 8) {
            uint32_t af[2][4], bf[4][2];
            #pragma unroll
            for (int mt = 0; mt < 2; mt++) {
                int r = wm + mt * 16 + g;
                af[mt][0] = tf32u(As[r * SMP + ks + q]);
                af[mt][1] = tf32u(As[(r + 8) * SMP + ks + q]);
                af[mt][2] = tf32u(As[r * SMP + ks + q + 4]);
                af[mt][3] = tf32u(As[(r + 8) * SMP + ks + q + 4]);
            }
            #pragma unroll
            for (int nt = 0; nt < 4; nt++) {
                int n = wn + nt * 8 + g;
                bf[nt][0] = tf32u(Vs[(ks + q) * VPV + n]);
                bf[nt][1] = tf32u(Vs[(ks + q + 4) * VPV + n]);
            }
            #pragma unroll
            for (int mt = 0; mt < 2; mt++)
                #pragma unroll
                for (int nt = 0; nt < 4; nt++)
                    mma_tf32(acc[mt][nt], af[mt], bf[nt]);
        }
    }

    const float* rz = rsum + (size_t)z * QLEN;
    #pragma unroll
    for (int mt = 0; mt < 2; mt++) {
        int m = i0 + wm + mt * 16 + g;
        float inv0 = 1.f / rz[m];
        float inv1 = 1.f / rz[m + 8];
        #pragma unroll
        for (int nt = 0; nt < 4; nt++) {
            int d = wn + nt * 8 + q * 2;
            size_t o0 = ((size_t)m * 4 + bb) * 1024 + hh * 64 + d;
            size_t o1 = ((size_t)(m + 8) * 4 + bb) * 1024 + hh * 64 + d;
            *(float2*)&ctx[o0] = make_float2(acc[mt][nt][0] * inv0, acc[mt][nt][1] * inv0);
            *(float2*)&ctx[o1] = make_float2(acc[mt][nt][2] * inv1, acc[mt][nt][3] * inv1);
        }
    }
}

// ---------------- Qu/Qv prep ----------------
__global__ void quv_prep(const float* __restrict__ qkv, const float* __restrict__ u,
                         const float* __restrict__ v, float* __restrict__ Qu,
                         float* __restrict__ Qv)
{
    size_t idx = (size_t)blockIdx.x * 256 + threadIdx.x;
    int d = idx & 63;
    size_t row = idx >> 6;
    int i = row & 1023;
    int z = row >> 10, bb = z >> 4, hh = z & 15;
    float qv = qkv[((size_t)((MEMLEN + i) * 4 + bb)) * 3072 + hh * 64 + d];
    Qu[idx] = qv + u[hh * 64 + d];
    Qv[idx] = qv + v[hh * 64 + d];
}

// ---------------- layernorm ----------------
__device__ __forceinline__ float block_sum256(float v, float* red)
{
    #pragma unroll
    for (int o = 16; o; o >>= 1) v += __shfl_xor_sync(0xffffffffu, v, o);
    if ((threadIdx.x & 31) == 0) red[threadIdx.x >> 5] = v;
    __syncthreads();
    float s = 0.f;
    #pragma unroll
    for (int w = 0; w < 8; w++) s += red[w];
    __syncthreads();
    return s;
}

__global__ void ln_kernel(const float* __restrict__ A, const float* __restrict__ Bv,
                          const float* __restrict__ g, const float* __restrict__ be,
                          float* __restrict__ out)
{
    int row = blockIdx.x;
    int t = threadIdx.x;
    __shared__ float red[8];
    size_t base = (size_t)row * DMODEL;

    float x[4];
    float s = 0.f;
    #pragma unroll
    for (int r = 0; r < 4; r++) {
        int c = t + r * 256;
        x[r] = A[base + c] + Bv[base + c];
        s += x[r];
    }
    float mean = block_sum256(s, red) * (1.f / DMODEL);

    float q = 0.f;
    #pragma unroll
    for (int r = 0; r < 4; r++) {
        float d = x[r] - mean;
        q += d * d;
    }
    float var = block_sum256(q, red) * (1.f / DMODEL);
    float rstd = rsqrtf(var + 1e-5f);

    #pragma unroll
    for (int r = 0; r < 4; r++) {
        int c = t + r * 256;
        out[base + c] = (x[r] - mean) * rstd * g[c] + be[c];
    }
}

// ---------------- host orchestration ----------------
extern "C" void kernel_launch(void* const* d_in, const int* in_sizes, int n_in,
                              void* d_out, int out_size)
{
    (void)in_sizes; (void)out_size;
    int off = (n_in >= 17) ? 0 : -1;
    const float* inp   = (const float*)d_in[0];
    const float* r     = (const float*)d_in[1];
    const float* u     = (const float*)d_in[2];
    const float* v     = (const float*)d_in[3];
    const float* mem   = (const float*)d_in[4];
    const float* W_qkv = (const float*)d_in[6 + off];
    const float* W_r   = (const float*)d_in[7 + off];
    const float* W_o   = (const float*)d_in[8 + off];
    const float* ln1g  = (const float*)d_in[9 + off];
    const float* ln1b  = (const float*)d_in[10 + off];
    const float* ln2g  = (const float*)d_in[11 + off];
    const float* ln2b  = (const float*)d_in[12 + off];
    const float* W1    = (const float*)d_in[13 + off];
    const float* b1    = (const float*)d_in[14 + off];
    const float* W2    = (const float*)d_in[15 + off];
    const float* b2    = (const float*)d_in[16 + off];
    float* out = (float*)d_out;

    float *cat_p, *qkv_p, *rh_p, *S_p, *BD_p, *Qu_p, *Qv_p, *rs_p, *ctx_p, *y_p, *x_p, *h_p, *y2_p;
    cudaGetSymbolAddress((void**)&cat_p, g_cat);
    cudaGetSymbolAddress((void**)&qkv_p, g_qkv);
    cudaGetSymbolAddress((void**)&rh_p,  g_rh);
    cudaGetSymbolAddress((void**)&S_p,   g_S);
    cudaGetSymbolAddress((void**)&BD_p,  g_BD);
    cudaGetSymbolAddress((void**)&Qu_p,  g_Qu);
    cudaGetSymbolAddress((void**)&Qv_p,  g_Qv);
    cudaGetSymbolAddress((void**)&rs_p,  g_rsum);
    cudaGetSymbolAddress((void**)&ctx_p, g_ctx);
    cudaGetSymbolAddress((void**)&y_p,   g_y);
    cudaGetSymbolAddress((void**)&x_p,   g_x);
    cudaGetSymbolAddress((void**)&h_p,   g_h);
    cudaGetSymbolAddress((void**)&y2_p,  g_y2);

    cudaFuncSetAttribute(mm_nn,   cudaFuncAttributeMaxDynamicSharedMemorySize, NN_SMEM);
    cudaFuncSetAttribute(mm_nt,   cudaFuncAttributeMaxDynamicSharedMemorySize, NT_SMEM);
    cudaFuncSetAttribute(ac_fused, cudaFuncAttributeMaxDynamicSharedMemorySize, NT_SMEM);
    cudaFuncSetAttribute(pv_mma,  cudaFuncAttributeMaxDynamicSharedMemorySize, PV_SMEM);

    // cat = [mem; inputs]
    cudaMemcpyAsync(cat_p, mem, (size_t)MEMLEN * BATCH * DMODEL * sizeof(float),
                    cudaMemcpyDeviceToDevice);
    cudaMemcpyAsync(cat_p + (size_t)MEMLEN * BATCH * DMODEL, inp,
                    (size_t)QLEN * BATCH * DMODEL * sizeof(float),
                    cudaMemcpyDeviceToDevice);
    cudaMemsetAsync(rs_p, 0, (size_t)64 * QLEN * sizeof(float));

    dim3 blk(256);
    // qkv = cat @ W_qkv  (weights consumed in [K,N] directly)
    mm_nn<<<dim3(3072/128, 6144/128), blk, NN_SMEM>>>(
        cat_p, W_qkv, qkv_p, 6144, 3072, 1024, 1024, 3072, 3072, nullptr, 0);
    // r_h = r @ W_r
    mm_nn<<<dim3(1024/128, 1536/128), blk, NN_SMEM>>>(
        r, W_r, rh_p, 1536, 1024, 1024, 1024, 1024, 1024, nullptr, 0);
    // Qu/Qv prep
    quv_prep<<<(64 * QLEN * HDIM) / 256, 256>>>(qkv_p, u, v, Qu_p, Qv_p);
    // BD[z] = Qv @ rh[:, h*64:h*64+64]^T, dead tiles skipped
    mm_nt<<<dim3(1536/128, 1024/128, 64), blk, NT_SMEM>>>(
        Qv_p, rh_p, BD_p, 1024, 1536, 64, 64, 1024, 1536,
        (long)1024*64, 64, (long)1024*1536, 769);
    // P = exp(mask(AC + shift(BD)) * scale), rowsum -> rsum
    ac_fused<<<dim3(1536/128, 1024/128, 64), blk, NT_SMEM>>>(
        Qu_p, qkv_p, BD_p, S_p, rs_p);
    // ctx = (P @ V) / rsum
    pv_mma<<<dim3(QLEN/128, 64), blk, PV_SMEM>>>(S_p, qkv_p, rs_p, ctx_p);
    // y = ctx @ W_o
    mm_nn<<<dim3(1024/128, 4096/128), blk, NN_SMEM>>>(
        ctx_p, W_o, y_p, 4096, 1024, 1024, 1024, 1024, 1024, nullptr, 0);
    ln_kernel<<<NROWS, 256>>>(inp, y_p, ln1g, ln1b, x_p);
    // h = relu(x @ W1 + b1)
    mm_nn<<<dim3(4096/128, 4096/128), blk, NN_SMEM>>>(
        x_p, W1, h_p, 4096, 4096, 1024, 1024, 4096, 4096, b1, 1);
    // y2 = h @ W2 + b2
    mm_nn<<<dim3(1024/128, 4096/128), blk, NN_SMEM>>>(
        h_p, W2, y2_p, 4096, 1024, 4096, 4096, 1024, 1024, b2, 0);
    ln_kernel<<<NROWS, 256>>>(x_p, y2_p, ln2g, ln2b, out);
}